// round 8
// baseline (speedup 1.0000x reference)
#include <cuda_runtime.h>

// RLGate: B=4, T=2048, D=1024, E=8, K=2
// 512-thread CTA (2 dims/thread) to cut regs -> 3 CTAs/SM (48 warps resident).
// Fused: logits -> softmax+gumbel top2 -> gather/average; aux via last block.

#define BB      4
#define TT      2048
#define DD      1024
#define EE      8
#define NTOK    (BB * TT)          // 8192
#define TPB_TOK 8                   // tokens per CTA
#define NCTA    (NTOK / TPB_TOK)    // 1024
#define NW      16                  // warps per CTA
#define EPSF    1e-9f
#define FULLM   0xFFFFFFFFu

__device__ float g_contrib[NCTA];
__device__ int   g_count = 0;

__global__ __launch_bounds__(512, 3) void rlgate_kernel(
    const float* __restrict__ x,
    const float* __restrict__ eo,
    const float* __restrict__ rewards,
    const float* __restrict__ W,
    const float* __restrict__ bias,
    const float* __restrict__ baseline,
    const float* __restrict__ noise_u,
    float* __restrict__ out)
{
    const int tid  = threadIdx.x;
    const int lane = tid & 31;
    const int warp = tid >> 5;
    const int tokBase = blockIdx.x * TPB_TOK;

    __shared__ __align__(16) float Wt[EE][1024];     // transposed W
    __shared__ float part[TPB_TOK][NW * EE];          // per-warp expert partials
    __shared__ float logit_s[TPB_TOK][EE];
    __shared__ int   sidx_s[TPB_TOK][2];
    __shared__ float contrib_s[TPB_TOK];

    // ---- Phase 0: stage W -> smem transposed (coalesced) ----
    const float4* W4 = reinterpret_cast<const float4*>(W);   // 2048 float4
    #pragma unroll
    for (int k = 0; k < 4; k++) {
        int idx = tid + 512 * k;
        float4 wv = W4[idx];
        int d  = idx >> 1;
        int e0 = (idx & 1) * 4;
        Wt[e0 + 0][d] = wv.x;
        Wt[e0 + 1][d] = wv.y;
        Wt[e0 + 2][d] = wv.z;
        Wt[e0 + 3][d] = wv.w;
    }
    __syncthreads();

    // this thread's 2 dims of W for all 8 experts: 16 regs
    float2 wr[EE];
    #pragma unroll
    for (int e = 0; e < EE; e++)
        wr[e] = *reinterpret_cast<const float2*>(&Wt[e][2 * tid]);

    // ---- Phase 1: logits partials; x float2 loads, batch 4 tokens ----
    const float2* X2 = reinterpret_cast<const float2*>(x);
    #pragma unroll
    for (int tb = 0; tb < TPB_TOK; tb += 4) {
        float2 xv[4];
        #pragma unroll
        for (int j = 0; j < 4; j++)
            xv[j] = __ldcs(&X2[(size_t)(tokBase + tb + j) * (DD / 2) + tid]);

        #pragma unroll
        for (int j = 0; j < 4; j++) {
            const int t = tb + j;
            float v[EE];
            #pragma unroll
            for (int e = 0; e < EE; e++)
                v[e] = fmaf(xv[j].x, wr[e].x, xv[j].y * wr[e].y);

            // 16-shuffle multi-value warp reduction (split after each round)
            #pragma unroll
            for (int e = 0; e < EE; e++) v[e] += __shfl_xor_sync(FULLM, v[e], 16);
            if (lane & 16) { v[0] = v[4]; v[1] = v[5]; v[2] = v[6]; v[3] = v[7]; }
            #pragma unroll
            for (int i = 0; i < 4; i++)  v[i] += __shfl_xor_sync(FULLM, v[i], 8);
            if (lane & 8)  { v[0] = v[2]; v[1] = v[3]; }
            #pragma unroll
            for (int i = 0; i < 2; i++)  v[i] += __shfl_xor_sync(FULLM, v[i], 4);
            if (lane & 4)  { v[0] = v[1]; }
            v[0] += __shfl_xor_sync(FULLM, v[0], 2);
            v[0] += __shfl_xor_sync(FULLM, v[0], 1);
            if ((lane & 3) == 0) part[t][warp * EE + (lane >> 2)] = v[0];
        }
    }
    __syncthreads();

    // ---- Phase 2a: cross-warp sum -> logits (64 threads) ----
    if (tid < TPB_TOK * EE) {
        const int t = tid >> 3, e = tid & 7;
        float s = bias[e];
        #pragma unroll
        for (int w = 0; w < NW; w++) s += part[t][w * EE + e];
        logit_s[t][e] = s;
    }
    __syncthreads();

    // ---- Phase 2b: one thread per (token, expert); 8-lane groups ----
    if (tid < TPB_TOK * EE) {
        const int t = tid >> 3, e = tid & 7;
        const int tok = tokBase + t;
        const float l = logit_s[t][e];

        float mx = l;
        #pragma unroll
        for (int off = 4; off > 0; off >>= 1)
            mx = fmaxf(mx, __shfl_xor_sync(FULLM, mx, off));
        float p = __expf(l - mx);
        float ps = p;
        #pragma unroll
        for (int off = 4; off > 0; off >>= 1)
            ps += __shfl_xor_sync(FULLM, ps, off);

        const float lp = logf(p / ps + EPSF);
        const float u  = noise_u[(size_t)tok * EE + e] * (1.0f - 2e-7f) + 1e-7f;
        const float sc = lp - logf(-logf(u));

        // butterfly top-2 (strict '>' / lowest index)
        float m1 = sc, m2 = -__int_as_float(0x7F800000);
        int   i1 = e,  i2 = 8;
        #pragma unroll
        for (int off = 4; off > 0; off >>= 1) {
            float om1 = __shfl_xor_sync(FULLM, m1, off);
            int   oi1 = __shfl_xor_sync(FULLM, i1, off);
            float om2 = __shfl_xor_sync(FULLM, m2, off);
            int   oi2 = __shfl_xor_sync(FULLM, i2, off);
            const bool aFirst = (m1 > om1) || (m1 == om1 && i1 < oi1);
            float n1, n2; int ni1, ni2;
            if (aFirst) {
                n1 = m1; ni1 = i1;
                const bool s = (m2 > om1) || (m2 == om1 && i2 < oi1);
                n2 = s ? m2 : om1; ni2 = s ? i2 : oi1;
            } else {
                n1 = om1; ni1 = oi1;
                const bool s = (om2 > m1) || (om2 == m1 && oi2 < i1);
                n2 = s ? om2 : m1; ni2 = s ? oi2 : i1;
            }
            m1 = n1; i1 = ni1; m2 = n2; i2 = ni2;
        }

        const int gbase = lane & ~7;
        const float lp0 = __shfl_sync(FULLM, lp, gbase + i1);
        const float lp1 = __shfl_sync(FULLM, lp, gbase + i2);

        if (e == 0) {
            sidx_s[t][0] = i1;
            sidx_s[t][1] = i2;
            const float adv = rewards[tok] - baseline[0];
            contrib_s[t] = -(adv * (lp0 + lp1)) * (1.0f / (float)NTOK);
        }
    }
    __syncthreads();

    // warp 0: publish per-CTA aux partial, grab last-CTA ticket
    bool isLast = false;
    if (warp == 0) {
        float c = (lane < TPB_TOK) ? contrib_s[lane] : 0.0f;
        #pragma unroll
        for (int off = 4; off > 0; off >>= 1)
            c += __shfl_xor_sync(FULLM, c, off);
        if (lane == 0) {
            g_contrib[blockIdx.x] = c;
            __threadfence();
            isLast = (atomicAdd(&g_count, 1) == NCTA - 1);
        }
        isLast = __shfl_sync(FULLM, isLast ? 1 : 0, 0) != 0;
    }

    // ---- Phase 3: gather 2 expert rows/token, average, write ----
    // sub = tid>>8 picks token subset {0..3}/{4..7}; col covers full row.
    const float4* EO4 = reinterpret_cast<const float4*>(eo);
    float4* OUT4 = reinterpret_cast<float4*>(out);
    const int sub = tid >> 8;          // 0 or 1
    const int col = tid & 255;         // float4 column in row
    #pragma unroll
    for (int it = 0; it < 4; it += 2) {
        float4 a[2], c4[2];
        #pragma unroll
        for (int j = 0; j < 2; j++) {
            const int t = sub * 4 + it + j;
            const size_t base4 = (size_t)(tokBase + t) * (DD / 4) + col;
            a[j]  = __ldcs(&EO4[(size_t)sidx_s[t][0] * NTOK * (DD / 4) + base4]);
            c4[j] = __ldcs(&EO4[(size_t)sidx_s[t][1] * NTOK * (DD / 4) + base4]);
        }
        #pragma unroll
        for (int j = 0; j < 2; j++) {
            const int t = sub * 4 + it + j;
            const size_t base4 = (size_t)(tokBase + t) * (DD / 4) + col;
            float4 r;
            r.x = (a[j].x + c4[j].x) * 0.5f;
            r.y = (a[j].y + c4[j].y) * 0.5f;
            r.z = (a[j].z + c4[j].z) * 0.5f;
            r.w = (a[j].w + c4[j].w) * 0.5f;
            __stcs(&OUT4[base4], r);
        }
    }

    // last CTA: reduce all per-CTA aux partials (deterministic set)
    if (warp == 0 && isLast) {
        __threadfence();
        float ssum = 0.0f;
        #pragma unroll
        for (int k = 0; k < NCTA / 32; k++)
            ssum += g_contrib[lane + 32 * k];
        #pragma unroll
        for (int off = 16; off > 0; off >>= 1)
            ssum += __shfl_down_sync(FULLM, ssum, off);
        if (lane == 0) {
            out[(size_t)NTOK * DD] = ssum;
            g_count = 0;                      // reset for next graph replay
        }
    }
}

extern "C" void kernel_launch(void* const* d_in, const int* in_sizes, int n_in,
                              void* d_out, int out_size) {
    const float* x        = (const float*)d_in[0];
    const float* eo       = (const float*)d_in[1];
    const float* rewards  = (const float*)d_in[2];
    const float* W        = (const float*)d_in[3];
    const float* bias     = (const float*)d_in[4];
    const float* baseline = (const float*)d_in[5];
    const float* noise_u  = (const float*)d_in[6];
    float* out = (float*)d_out;

    rlgate_kernel<<<NCTA, 512>>>(x, eo, rewards, W, bias, baseline, noise_u, out);
}

// round 9
// speedup vs baseline: 1.0428x; 1.0428x over previous
#include <cuda_runtime.h>

// RLGate: B=4, T=2048, D=1024, E=8, K=2
// 256-thread CTA, float4 path, W kept in smem (asm LDS, no reg hoist) to cut
// regs -> 6 CTAs/SM. Fused logits -> gumbel top2 -> gather; aux via last block.

#define BB      4
#define TT      2048
#define DD      1024
#define EE      8
#define NTOK    (BB * TT)          // 8192
#define TPB_TOK 8                   // tokens per CTA
#define NCTA    (NTOK / TPB_TOK)    // 1024
#define EPSF    1e-9f
#define FULLM   0xFFFFFFFFu

__device__ float g_contrib[NCTA];
__device__ int   g_count = 0;

__global__ __launch_bounds__(256, 6) void rlgate_kernel(
    const float* __restrict__ x,
    const float* __restrict__ eo,
    const float* __restrict__ rewards,
    const float* __restrict__ W,
    const float* __restrict__ bias,
    const float* __restrict__ baseline,
    const float* __restrict__ noise_u,
    float* __restrict__ out)
{
    const int tid  = threadIdx.x;
    const int lane = tid & 31;
    const int warp = tid >> 5;
    const int tokBase = blockIdx.x * TPB_TOK;

    __shared__ __align__(16) float Wt[EE][1024];     // transposed W (4KB rows)
    __shared__ float part[TPB_TOK][64];
    __shared__ float logit_s[TPB_TOK][EE];
    __shared__ int   sidx_s[TPB_TOK][2];
    __shared__ float contrib_s[TPB_TOK];

    // ---- Phase 0: stage W -> smem transposed (coalesced) ----
    const float4* W4 = reinterpret_cast<const float4*>(W);   // 2048 float4
    #pragma unroll
    for (int k = 0; k < 8; k++) {
        int idx = tid + 256 * k;
        float4 wv = W4[idx];
        int d  = idx >> 1;
        int e0 = (idx & 1) * 4;
        Wt[e0 + 0][d] = wv.x;
        Wt[e0 + 1][d] = wv.y;
        Wt[e0 + 2][d] = wv.z;
        Wt[e0 + 3][d] = wv.w;
    }
    __syncthreads();

    // smem address of this thread's W slice (dims 4*tid..4*tid+3, expert 0)
    const unsigned wbase =
        (unsigned)__cvta_generic_to_shared(&Wt[0][4 * tid]);

    // ---- Phase 1: logits partials; batch 2 tokens; W via asm LDS ----
    const float4* X4 = reinterpret_cast<const float4*>(x);
    #pragma unroll
    for (int tb = 0; tb < TPB_TOK; tb += 2) {
        float4 xv[2];
        #pragma unroll
        for (int j = 0; j < 2; j++)
            xv[j] = __ldcs(&X4[(size_t)(tokBase + tb + j) * (DD / 4) + tid]);

        #pragma unroll
        for (int j = 0; j < 2; j++) {
            const int t = tb + j;
            float v[EE];
            #pragma unroll
            for (int e = 0; e < EE; e++) {
                float w0, w1, w2, w3;
                asm volatile("ld.shared.v4.f32 {%0,%1,%2,%3}, [%4];"
                             : "=f"(w0), "=f"(w1), "=f"(w2), "=f"(w3)
                             : "r"(wbase + e * 4096));
                float s = xv[j].x * w0;
                s = fmaf(xv[j].y, w1, s);
                s = fmaf(xv[j].z, w2, s);
                v[e] = fmaf(xv[j].w, w3, s);
            }
            // 16-shuffle multi-value warp reduction (split after each round)
            #pragma unroll
            for (int e = 0; e < EE; e++) v[e] += __shfl_xor_sync(FULLM, v[e], 16);
            if (lane & 16) { v[0] = v[4]; v[1] = v[5]; v[2] = v[6]; v[3] = v[7]; }
            #pragma unroll
            for (int i = 0; i < 4; i++)  v[i] += __shfl_xor_sync(FULLM, v[i], 8);
            if (lane & 8)  { v[0] = v[2]; v[1] = v[3]; }
            #pragma unroll
            for (int i = 0; i < 2; i++)  v[i] += __shfl_xor_sync(FULLM, v[i], 4);
            if (lane & 4)  { v[0] = v[1]; }
            v[0] += __shfl_xor_sync(FULLM, v[0], 2);
            v[0] += __shfl_xor_sync(FULLM, v[0], 1);
            if ((lane & 3) == 0) part[t][warp * 8 + (lane >> 2)] = v[0];
        }
    }
    __syncthreads();

    // ---- Phase 2a: cross-warp sum -> logits (64 threads) ----
    if (tid < TPB_TOK * EE) {
        const int t = tid >> 3, e = tid & 7;
        float s = bias[e];
        #pragma unroll
        for (int w = 0; w < 8; w++) s += part[t][w * 8 + e];
        logit_s[t][e] = s;
    }
    __syncthreads();

    // ---- Phase 2b: one thread per (token, expert); 8-lane groups ----
    if (tid < TPB_TOK * EE) {
        const int t = tid >> 3, e = tid & 7;
        const int tok = tokBase + t;
        const float l = logit_s[t][e];

        float mx = l;
        #pragma unroll
        for (int off = 4; off > 0; off >>= 1)
            mx = fmaxf(mx, __shfl_xor_sync(FULLM, mx, off));
        float p = __expf(l - mx);
        float ps = p;
        #pragma unroll
        for (int off = 4; off > 0; off >>= 1)
            ps += __shfl_xor_sync(FULLM, ps, off);

        const float lp = logf(p / ps + EPSF);
        const float u  = noise_u[(size_t)tok * EE + e] * (1.0f - 2e-7f) + 1e-7f;
        const float sc = lp - logf(-logf(u));

        // butterfly top-2 (strict '>' / lowest index)
        float m1 = sc, m2 = -__int_as_float(0x7F800000);
        int   i1 = e,  i2 = 8;
        #pragma unroll
        for (int off = 4; off > 0; off >>= 1) {
            float om1 = __shfl_xor_sync(FULLM, m1, off);
            int   oi1 = __shfl_xor_sync(FULLM, i1, off);
            float om2 = __shfl_xor_sync(FULLM, m2, off);
            int   oi2 = __shfl_xor_sync(FULLM, i2, off);
            const bool aFirst = (m1 > om1) || (m1 == om1 && i1 < oi1);
            float n1, n2; int ni1, ni2;
            if (aFirst) {
                n1 = m1; ni1 = i1;
                const bool s = (m2 > om1) || (m2 == om1 && i2 < oi1);
                n2 = s ? m2 : om1; ni2 = s ? i2 : oi1;
            } else {
                n1 = om1; ni1 = oi1;
                const bool s = (om2 > m1) || (om2 == m1 && oi2 < i1);
                n2 = s ? om2 : m1; ni2 = s ? oi2 : i1;
            }
            m1 = n1; i1 = ni1; m2 = n2; i2 = ni2;
        }

        const int gbase = lane & ~7;
        const float lp0 = __shfl_sync(FULLM, lp, gbase + i1);
        const float lp1 = __shfl_sync(FULLM, lp, gbase + i2);

        if (e == 0) {
            sidx_s[t][0] = i1;
            sidx_s[t][1] = i2;
            const float adv = rewards[tok] - baseline[0];
            contrib_s[t] = -(adv * (lp0 + lp1)) * (1.0f / (float)NTOK);
        }
    }
    __syncthreads();

    // warp 0: publish per-CTA aux partial, grab last-CTA ticket
    bool isLast = false;
    if (warp == 0) {
        float c = (lane < TPB_TOK) ? contrib_s[lane] : 0.0f;
        #pragma unroll
        for (int off = 4; off > 0; off >>= 1)
            c += __shfl_xor_sync(FULLM, c, off);
        if (lane == 0) {
            g_contrib[blockIdx.x] = c;
            __threadfence();
            isLast = (atomicAdd(&g_count, 1) == NCTA - 1);
        }
        isLast = __shfl_sync(FULLM, isLast ? 1 : 0, 0) != 0;
    }

    // ---- Phase 3: gather 2 expert rows/token, average, write (batch 2) ----
    const float4* EO4 = reinterpret_cast<const float4*>(eo);
    float4* OUT4 = reinterpret_cast<float4*>(out);
    #pragma unroll
    for (int tb = 0; tb < TPB_TOK; tb += 2) {
        float4 a[2], c4[2];
        #pragma unroll
        for (int j = 0; j < 2; j++) {
            const int t = tb + j;
            const size_t base4 = (size_t)(tokBase + t) * (DD / 4) + tid;
            a[j]  = __ldcs(&EO4[(size_t)sidx_s[t][0] * NTOK * (DD / 4) + base4]);
            c4[j] = __ldcs(&EO4[(size_t)sidx_s[t][1] * NTOK * (DD / 4) + base4]);
        }
        #pragma unroll
        for (int j = 0; j < 2; j++) {
            const int t = tb + j;
            const size_t base4 = (size_t)(tokBase + t) * (DD / 4) + tid;
            float4 r;
            r.x = (a[j].x + c4[j].x) * 0.5f;
            r.y = (a[j].y + c4[j].y) * 0.5f;
            r.z = (a[j].z + c4[j].z) * 0.5f;
            r.w = (a[j].w + c4[j].w) * 0.5f;
            __stcs(&OUT4[base4], r);
        }
    }

    // last CTA: reduce all per-CTA aux partials (deterministic set)
    if (warp == 0 && isLast) {
        __threadfence();
        float ssum = 0.0f;
        #pragma unroll
        for (int k = 0; k < NCTA / 32; k++)
            ssum += g_contrib[lane + 32 * k];
        #pragma unroll
        for (int off = 16; off > 0; off >>= 1)
            ssum += __shfl_down_sync(FULLM, ssum, off);
        if (lane == 0) {
            out[(size_t)NTOK * DD] = ssum;
            g_count = 0;                      // reset for next graph replay
        }
    }
}

extern "C" void kernel_launch(void* const* d_in, const int* in_sizes, int n_in,
                              void* d_out, int out_size) {
    const float* x        = (const float*)d_in[0];
    const float* eo       = (const float*)d_in[1];
    const float* rewards  = (const float*)d_in[2];
    const float* W        = (const float*)d_in[3];
    const float* bias     = (const float*)d_in[4];
    const float* baseline = (const float*)d_in[5];
    const float* noise_u  = (const float*)d_in[6];
    float* out = (float*)d_out;

    rlgate_kernel<<<NCTA, 256>>>(x, eo, rewards, W, bias, baseline, noise_u, out);
}

// round 10
// speedup vs baseline: 1.3254x; 1.2709x over previous
#include <cuda_runtime.h>

// RLGate: B=4, T=2048, D=1024, E=8, K=2
// Warp-autonomous: each warp owns 2 tokens end-to-end (logits -> gumbel top2
// -> gather). No mid-kernel barriers; aux loss via end-of-CTA reduce +
// last-block finalize.

#define BB      4
#define TT      2048
#define DD      1024
#define EE      8
#define NTOK    (BB * TT)          // 8192
#define TPB_TOK 16                  // tokens per CTA (8 warps x 2)
#define NCTA    (NTOK / TPB_TOK)    // 512
#define EPSF    1e-9f
#define FULLM   0xFFFFFFFFu

__device__ float g_contrib[NCTA];
__device__ int   g_count = 0;

// 16-shuffle split reduction: on return lane 4*e holds sum over warp of v[e]
__device__ __forceinline__ float warp_reduce8(float v[EE], int lane) {
    #pragma unroll
    for (int e = 0; e < EE; e++) v[e] += __shfl_xor_sync(FULLM, v[e], 16);
    if (lane & 16) { v[0] = v[4]; v[1] = v[5]; v[2] = v[6]; v[3] = v[7]; }
    #pragma unroll
    for (int i = 0; i < 4; i++)  v[i] += __shfl_xor_sync(FULLM, v[i], 8);
    if (lane & 8)  { v[0] = v[2]; v[1] = v[3]; }
    #pragma unroll
    for (int i = 0; i < 2; i++)  v[i] += __shfl_xor_sync(FULLM, v[i], 4);
    if (lane & 4)  { v[0] = v[1]; }
    v[0] += __shfl_xor_sync(FULLM, v[0], 2);
    v[0] += __shfl_xor_sync(FULLM, v[0], 1);
    return v[0];
}

__global__ __launch_bounds__(256) void rlgate_kernel(
    const float* __restrict__ x,
    const float* __restrict__ eo,
    const float* __restrict__ rewards,
    const float* __restrict__ W,
    const float* __restrict__ bias,
    const float* __restrict__ baseline,
    const float* __restrict__ noise_u,
    float* __restrict__ out)
{
    const int tid  = threadIdx.x;
    const int lane = tid & 31;
    const int warp = tid >> 5;

    __shared__ __align__(16) float Wt[EE][1024];   // transposed W
    __shared__ float bias_s[EE];
    __shared__ float contrib_s[8];

    // ---- stage W -> smem transposed (coalesced) ----
    const float4* W4 = reinterpret_cast<const float4*>(W);   // 2048 float4
    #pragma unroll
    for (int k = 0; k < 8; k++) {
        int idx = tid + 256 * k;
        float4 wv = W4[idx];
        int d  = idx >> 1;
        int e0 = (idx & 1) * 4;
        Wt[e0 + 0][d] = wv.x;
        Wt[e0 + 1][d] = wv.y;
        Wt[e0 + 2][d] = wv.z;
        Wt[e0 + 3][d] = wv.w;
    }
    if (tid < EE) bias_s[tid] = bias[tid];
    __syncthreads();

    // ---- this warp's 2 tokens ----
    const int t0 = blockIdx.x * TPB_TOK + warp * 2;   // t1 = t0 + 1
    const float4* X4 = reinterpret_cast<const float4*>(x);
    const size_t xoff = (size_t)t0 * (DD / 4) + lane;

    float acc0[EE], acc1[EE];
    #pragma unroll
    for (int e = 0; e < EE; e++) { acc0[e] = 0.0f; acc1[e] = 0.0f; }

    // chunked dot products with one-chunk prefetch (MLP >= 4)
    float4 xa = __ldcs(&X4[xoff]);
    float4 xb = __ldcs(&X4[xoff + (DD / 4)]);
    #pragma unroll
    for (int k = 0; k < 8; k++) {
        float4 na, nb;
        if (k < 7) {
            na = __ldcs(&X4[xoff + 32 * (k + 1)]);
            nb = __ldcs(&X4[xoff + (DD / 4) + 32 * (k + 1)]);
        }
        #pragma unroll
        for (int e = 0; e < EE; e++) {
            const float4 w = *reinterpret_cast<const float4*>(
                &Wt[e][(lane + 32 * k) * 4]);
            float s0 = xa.x * w.x;
            s0 = fmaf(xa.y, w.y, s0);
            s0 = fmaf(xa.z, w.z, s0);
            acc0[e] = fmaf(xa.w, w.w, acc0[e] + s0);
            float s1 = xb.x * w.x;
            s1 = fmaf(xb.y, w.y, s1);
            s1 = fmaf(xb.z, w.z, s1);
            acc1[e] = fmaf(xb.w, w.w, acc1[e] + s1);
        }
        xa = na; xb = nb;
    }

    const float r0 = warp_reduce8(acc0, lane);   // lane 4e: token0 expert e
    const float r1 = warp_reduce8(acc1, lane);   // lane 4e: token1 expert e

    // redistribute: 8-lane groups; groups {0,2} do token0, {1,3} do token1
    const int e   = lane & 7;
    const int grp = (lane >> 3) & 1;             // 0 -> t0, 1 -> t1
    const int tok = t0 + grp;
    const float l0 = __shfl_sync(FULLM, r0, 4 * e);
    const float l1 = __shfl_sync(FULLM, r1, 4 * e);
    const float logit = (grp ? l1 : l0) + bias_s[e];

    // ---- softmax + gumbel + top-2 within 8-lane group ----
    float mx = logit;
    #pragma unroll
    for (int off = 4; off > 0; off >>= 1)
        mx = fmaxf(mx, __shfl_xor_sync(FULLM, mx, off));
    float p = __expf(logit - mx);
    float ps = p;
    #pragma unroll
    for (int off = 4; off > 0; off >>= 1)
        ps += __shfl_xor_sync(FULLM, ps, off);

    const float lp = logf(p / ps + EPSF);
    const float u  = noise_u[(size_t)tok * EE + e] * (1.0f - 2e-7f) + 1e-7f;
    const float sc = lp - logf(-logf(u));

    // butterfly top-2 (strict '>' / lowest index)
    float m1 = sc, m2 = -__int_as_float(0x7F800000);
    int   i1 = e,  i2 = 8;
    #pragma unroll
    for (int off = 4; off > 0; off >>= 1) {
        float om1 = __shfl_xor_sync(FULLM, m1, off);
        int   oi1 = __shfl_xor_sync(FULLM, i1, off);
        float om2 = __shfl_xor_sync(FULLM, m2, off);
        int   oi2 = __shfl_xor_sync(FULLM, i2, off);
        const bool aFirst = (m1 > om1) || (m1 == om1 && i1 < oi1);
        float n1, n2; int ni1, ni2;
        if (aFirst) {
            n1 = m1; ni1 = i1;
            const bool s = (m2 > om1) || (m2 == om1 && i2 < oi1);
            n2 = s ? m2 : om1; ni2 = s ? i2 : oi1;
        } else {
            n1 = om1; ni1 = oi1;
            const bool s = (om2 > m1) || (om2 == m1 && oi2 < i1);
            n2 = s ? om2 : m1; ni2 = s ? oi2 : i1;
        }
        m1 = n1; i1 = ni1; m2 = n2; i2 = ni2;
    }

    // selected log-probs (group-local shuffle)
    const int gbase = lane & ~7;
    const float lpA = __shfl_sync(FULLM, lp, gbase + i1);
    const float lpB = __shfl_sync(FULLM, lp, gbase + i2);

    // aux contribution: take group leaders (lanes 0 and 8 only)
    const float adv = rewards[tok] - baseline[0];
    const float cme = -(adv * (lpA + lpB)) * (1.0f / (float)NTOK);
    const float ct  = __shfl_sync(FULLM, cme, 0) + __shfl_sync(FULLM, cme, 8);
    if (lane == 0) contrib_s[warp] = ct;

    // broadcast the 4 selected indices to the whole warp
    const int ia0 = __shfl_sync(FULLM, i1, 0);
    const int ib0 = __shfl_sync(FULLM, i2, 0);
    const int ia1 = __shfl_sync(FULLM, i1, 8);
    const int ib1 = __shfl_sync(FULLM, i2, 8);

    // ---- gather: 2 rows per token, average, write (MLP 8) ----
    const float4* EO4 = reinterpret_cast<const float4*>(eo);
    float4* OUT4 = reinterpret_cast<float4*>(out);
    #pragma unroll
    for (int tt = 0; tt < 2; tt++) {
        const int t  = t0 + tt;
        const int ia = tt ? ia1 : ia0;
        const int ib = tt ? ib1 : ib0;
        const size_t rowA = ((size_t)ia * NTOK + t) * (DD / 4) + lane;
        const size_t rowB = ((size_t)ib * NTOK + t) * (DD / 4) + lane;
        const size_t rowO = (size_t)t * (DD / 4) + lane;
        #pragma unroll
        for (int cb = 0; cb < 2; cb++) {
            float4 a[4], c4[4];
            #pragma unroll
            for (int j = 0; j < 4; j++) {
                a[j]  = __ldcs(&EO4[rowA + 32 * (4 * cb + j)]);
                c4[j] = __ldcs(&EO4[rowB + 32 * (4 * cb + j)]);
            }
            #pragma unroll
            for (int j = 0; j < 4; j++) {
                float4 r;
                r.x = (a[j].x + c4[j].x) * 0.5f;
                r.y = (a[j].y + c4[j].y) * 0.5f;
                r.z = (a[j].z + c4[j].z) * 0.5f;
                r.w = (a[j].w + c4[j].w) * 0.5f;
                __stcs(&OUT4[rowO + 32 * (4 * cb + j)], r);
            }
        }
    }

    // ---- aux finalize: CTA reduce + last-block global reduce ----
    __syncthreads();
    if (warp == 0) {
        float c = (lane < 8) ? contrib_s[lane] : 0.0f;
        #pragma unroll
        for (int off = 4; off > 0; off >>= 1)
            c += __shfl_xor_sync(FULLM, c, off);
        bool isLast = false;
        if (lane == 0) {
            g_contrib[blockIdx.x] = c;
            __threadfence();
            isLast = (atomicAdd(&g_count, 1) == NCTA - 1);
        }
        isLast = __shfl_sync(FULLM, isLast ? 1 : 0, 0) != 0;
        if (isLast) {
            __threadfence();
            float ssum = 0.0f;
            #pragma unroll
            for (int k = 0; k < NCTA / 32; k++)
                ssum += g_contrib[lane + 32 * k];
            #pragma unroll
            for (int off = 16; off > 0; off >>= 1)
                ssum += __shfl_down_sync(FULLM, ssum, off);
            if (lane == 0) {
                out[(size_t)NTOK * DD] = ssum;
                g_count = 0;                  // reset for next graph replay
            }
        }
    }
}

extern "C" void kernel_launch(void* const* d_in, const int* in_sizes, int n_in,
                              void* d_out, int out_size) {
    const float* x        = (const float*)d_in[0];
    const float* eo       = (const float*)d_in[1];
    const float* rewards  = (const float*)d_in[2];
    const float* W        = (const float*)d_in[3];
    const float* bias     = (const float*)d_in[4];
    const float* baseline = (const float*)d_in[5];
    const float* noise_u  = (const float*)d_in[6];
    float* out = (float*)d_out;

    rlgate_kernel<<<NCTA, 256>>>(x, eo, rewards, W, bias, baseline, noise_u, out);
}